// round 14
// baseline (speedup 1.0000x reference)
#include <cuda_runtime.h>
#include <cstdint>

#define NB 4
#define NS 2048
#define ND 128
#define NDL 16
#define NTOP 8

#define NSEG 64
#define QSEG (NS / NSEG)   // 32

#define KSPLIT 2
#define KPART (NS / KSPLIT)   // 1024
#define KC 32

typedef unsigned long long ull;

// ---- scratch (device globals; no allocation allowed) ----
__device__ float g_qlow[NB * NS * NDL];
__device__ float g_klow[NB * NS * NDL];
__device__ float g_sh[NB * NS];
__device__ float g_S[(size_t)NB * NS * NS];          // 64 MB corrected scores
__device__ float g_psum[NSEG * NB * NS];             // column partial sums
__device__ float g_cinv[NB * NS];
__device__ float g_po[KSPLIT][NB * NS * ND];         // split-k partial outputs

__device__ __forceinline__ float neg_inf() { return __int_as_float(0xff800000u); }

// ---- packed f32x2 helpers (FFMA2 path; ptxas won't emit this from C++) ----
__device__ __forceinline__ ull pack2(float lo, float hi) {
    ull r;
    asm("mov.b64 %0, {%1, %2};" : "=l"(r) : "f"(lo), "f"(hi));
    return r;
}
__device__ __forceinline__ ull pack2dup(float v) {
    ull r;
    asm("mov.b64 %0, {%1, %1};" : "=l"(r) : "f"(v));
    return r;
}
__device__ __forceinline__ void unpack2(ull v, float& lo, float& hi) {
    asm("mov.b64 {%0, %1}, %2;" : "=f"(lo), "=f"(hi) : "l"(v));
}
__device__ __forceinline__ void fma2(ull& acc, ull a, ull b) {
    asm("fma.rn.f32x2 %0, %1, %2, %0;" : "+l"(acc) : "l"(a), "l"(b));
}

// ============================================================
// K1: low/high projections + per-(b,k) correction scalar sh
// ============================================================
__global__ void __launch_bounds__(64) k_proj(
    const float* __restrict__ Q, const float* __restrict__ K,
    const float* __restrict__ Wql, const float* __restrict__ bql,
    const float* __restrict__ Wkl, const float* __restrict__ bkl,
    const float* __restrict__ Wqh, const float* __restrict__ bqh,
    const float* __restrict__ Wkh, const float* __restrict__ bkh)
{
    int row = blockIdx.x;          // b*NS + i
    int t = threadIdx.x;
    __shared__ float qr[ND];
    __shared__ float kr[ND];
    __shared__ float qh[NDL];
    __shared__ float kh[NDL];

    qr[t]      = Q[(size_t)row * ND + t];
    qr[t + 64] = Q[(size_t)row * ND + t + 64];
    kr[t]      = K[(size_t)row * ND + t];
    kr[t + 64] = K[(size_t)row * ND + t + 64];
    __syncthreads();

    int g = t >> 4, j = t & 15;
    if (g == 0) {
        float a = bql[j];
        #pragma unroll 8
        for (int e = 0; e < ND; e++) a += qr[e] * Wql[e * NDL + j];
        g_qlow[(size_t)row * NDL + j] = a;
    } else if (g == 1) {
        float a = bkl[j];
        #pragma unroll 8
        for (int e = 0; e < ND; e++) a += kr[e] * Wkl[e * NDL + j];
        g_klow[(size_t)row * NDL + j] = a;
    } else if (g == 2) {
        float a = bqh[j];
        #pragma unroll 8
        for (int e = 0; e < ND; e++) a += qr[e] * Wqh[e * NDL + j];
        qh[j] = a;
    } else {
        float a = bkh[j];
        #pragma unroll 8
        for (int e = 0; e < ND; e++) a += kr[e] * Wkh[e * NDL + j];
        kh[j] = a;
    }
    __syncthreads();

    if (t == 0) {
        float s = 0.f;
        #pragma unroll
        for (int j2 = 0; j2 < NDL; j2++) s += qh[j2] * kh[j2];
        g_sh[row] = 0.25f * s;    // scale = 1/sqrt(16)
    }
}

// ============================================================
// K2a: masked low-rank scores -> g_S  (f32x2 packed: 2 q rows per lane)
// ============================================================
__global__ void __launch_bounds__(256) k_scores(const int* __restrict__ VL)
{
    __shared__ __align__(16) float ks[128][20];
    __shared__ __align__(16) float Ss[32][132];
    __shared__ int vls[128];

    int b  = blockIdx.z;
    int q0 = blockIdx.y * 32;
    int k0 = blockIdx.x * 128;
    int t  = threadIdx.x;

    {
        const float4* src = (const float4*)(g_klow + ((size_t)b * NS + k0) * NDL);
        #pragma unroll
        for (int u = 0; u < 2; u++) {
            int p = t + u * 256;
            float4 v = src[p];
            *(float4*)&ks[p >> 2][(p & 3) * 4] = v;
        }
    }
    if (t < 128) {
        int vlc = VL[b * NS + k0 + t];
        vlc = vlc < 0 ? 0 : (vlc > NS - 1 ? NS - 1 : vlc);
        vls[t] = vlc;
    }
    __syncthreads();

    int tq = t >> 4;             // 0..15
    int kg = t & 15;             // 0..15
    int ql0 = tq * 2;
    int qg0 = q0 + ql0, qg1 = qg0 + 1;

    ull qp2[NDL];
    {
        const float4* qp = (const float4*)(g_qlow + ((size_t)b * NS + qg0) * NDL);
        #pragma unroll
        for (int u = 0; u < 4; u++) {
            float4 v = qp[u];       // row 0
            float4 w = qp[u + 4];   // row 1
            qp2[u * 4 + 0] = pack2(v.x, w.x);
            qp2[u * 4 + 1] = pack2(v.y, w.y);
            qp2[u * 4 + 2] = pack2(v.z, w.z);
            qp2[u * 4 + 3] = pack2(v.w, w.w);
        }
    }

    #pragma unroll
    for (int i = 0; i < 8; i++) {
        int kl = kg + 16 * i;
        ull acc = 0ull;
        #pragma unroll
        for (int u = 0; u < 4; u++) {
            float4 kv = *(const float4*)&ks[kl][u * 4];
            fma2(acc, qp2[u * 4 + 0], pack2dup(kv.x));
            fma2(acc, qp2[u * 4 + 1], pack2dup(kv.y));
            fma2(acc, qp2[u * 4 + 2], pack2dup(kv.z));
            fma2(acc, qp2[u * 4 + 3], pack2dup(kv.w));
        }
        float a0, a1;
        unpack2(acc, a0, a1);
        a0 *= 0.25f; a1 *= 0.25f;
        int vlc = vls[kl];
        if (vlc == qg0) a0 += -1e9f;
        if (vlc == qg1) a1 += -1e9f;
        Ss[ql0][kl]     = a0;
        Ss[ql0 + 1][kl] = a1;
    }
    __syncthreads();

    #pragma unroll
    for (int u = 0; u < 4; u++) {
        int p = t + u * 256;
        int row = p >> 5, cg = p & 31;
        float4 v = *(const float4*)&Ss[row][cg * 4];
        *(float4*)(g_S + ((size_t)b * NS + q0 + row) * NS + k0 + cg * 4) = v;
    }
}

// ============================================================
// K2b: per-row top-8 and scatter sh into g_S
// ============================================================
__global__ void __launch_bounds__(256) k_topk()
{
    int q = blockIdx.x, b = blockIdx.y;
    int t = threadIdx.x;
    __shared__ __align__(16) float wk[NS];
    __shared__ float rv[8];
    __shared__ int ri[8];
    __shared__ int s_mi;
    __shared__ int topIdx[NTOP];

    float* Srow = g_S + ((size_t)b * NS + q) * NS;
    #pragma unroll
    for (int u = 0; u < 2; u++) {
        int p = t + u * 256;
        ((float4*)wk)[p] = ((const float4*)Srow)[p];
    }
    __syncthreads();

    float lv = neg_inf(); int li = 0;
    #pragma unroll
    for (int i = 0; i < 8; i++) {
        int k = t + i * 256;
        float v = wk[k];
        if (v > lv) { lv = v; li = k; }
    }

    for (int r = 0; r < NTOP; r++) {
        float mv = lv; int mi = li;
        #pragma unroll
        for (int o = 16; o > 0; o >>= 1) {
            float ov = __shfl_xor_sync(0xffffffffu, mv, o);
            int   oi = __shfl_xor_sync(0xffffffffu, mi, o);
            if (ov > mv || (ov == mv && oi < mi)) { mv = ov; mi = oi; }
        }
        if ((t & 31) == 0) { rv[t >> 5] = mv; ri[t >> 5] = mi; }
        __syncthreads();
        if (t == 0) {
            #pragma unroll
            for (int w = 1; w < 8; w++)
                if (rv[w] > mv || (rv[w] == mv && ri[w] < mi)) { mv = rv[w]; mi = ri[w]; }
            topIdx[r] = mi;
            s_mi = mi;
        }
        __syncthreads();
        if (r < NTOP - 1) {
            int gm = s_mi;
            if ((gm & 255) == t) {      // only the owner rescans
                wk[gm] = neg_inf();
                lv = neg_inf(); li = 0;
                #pragma unroll
                for (int i = 0; i < 8; i++) {
                    int k = t + i * 256;
                    float v = wk[k];
                    if (v > lv) { lv = v; li = k; }
                }
            }
        }
    }

    if (t < NTOP) {
        int idx = topIdx[t];
        Srow[idx] = g_sh[b * NS + idx];
    }
}

// ============================================================
// K3a: partial column sum of exp over q-segments
// ============================================================
__global__ void __launch_bounds__(256) k_colpart()
{
    int k  = (blockIdx.x * 256 + threadIdx.x) * 4;
    int b  = blockIdx.y;
    int seg = blockIdx.z;
    const float* Sb = g_S + (size_t)b * NS * NS;
    int q0 = seg * QSEG;

    float4 s = make_float4(0.f, 0.f, 0.f, 0.f);
    #pragma unroll 4
    for (int q = q0; q < q0 + QSEG; q++) {
        float4 v = *(const float4*)&Sb[(size_t)q * NS + k];
        s.x += __expf(v.x);
        s.y += __expf(v.y);
        s.z += __expf(v.z);
        s.w += __expf(v.w);
    }
    *(float4*)&g_psum[((size_t)seg * NB + b) * NS + k] = s;
}

// K3b: combine segments -> 1/colsum
__global__ void __launch_bounds__(256) k_colfin()
{
    int i = blockIdx.x * 256 + threadIdx.x;   // b*NS + k
    float s = 0.f;
    #pragma unroll 8
    for (int seg = 0; seg < NSEG; seg++)
        s += g_psum[(size_t)seg * (NB * NS) + i];
    g_cinv[i] = 1.0f / s;
}

// ============================================================
// K4: split-k partial out = sum_k exp(S)*cinv[k]*V[b,k,:]
// 512 threads; block tile 128q x 128d; thread tile 4q x 8d; chunk 32k.
// Inner loop: 2 LDS128 (V) + 4 LDS64 bcast (A) per 16 FFMA2
//   -> 0.375 LDS/FFMA2 (vs 0.56 in all prior variants).
// Dynamic smem: As2[128][34] ull (34816 B) + Vs[32][128] f32 (16384 B).
// grid (NS/128, NB, KSPLIT) = 128 blocks = exactly one wave.
// ============================================================
#define ASTR 34
#define SMEM_OUT_BYTES (128 * ASTR * 8 + KC * ND * 4)   // 51200

__global__ void __launch_bounds__(512, 1) k_out(const float* __restrict__ V)
{
    extern __shared__ __align__(16) unsigned char smraw[];
    ull*   As2 = (ull*)smraw;                        // [128][ASTR]
    float* Vs  = (float*)(smraw + 128 * ASTR * 8);   // [KC][128]

    int b  = blockIdx.y;
    int q0 = blockIdx.x * 128;
    int z  = blockIdx.z;
    int t  = threadIdx.x;
    int tx = t & 15;     // d group: d = tx*8
    int ty = t >> 4;     // q group: q = q0 + ty*4 + qq   (0..31)

    const float* Sb = g_S + (size_t)b * NS * NS;
    const float* ci = g_cinv + b * NS;
    const float* Vb = V + (size_t)b * NS * ND;

    ull acc2[4][4];
    #pragma unroll
    for (int i = 0; i < 4; i++)
        #pragma unroll
        for (int j = 0; j < 4; j++) acc2[i][j] = 0ull;

    int kbeg = z * KPART, kend = kbeg + KPART;
    for (int k0 = kbeg; k0 < kend; k0 += KC) {
        __syncthreads();
        // ---- stage A: 128q x 32k, exp*cinv dup-packed (1024 float4, 2/thr) ----
        #pragma unroll
        for (int u = 0; u < 2; u++) {
            int p = t + u * 512;
            int row = p >> 3, kg = (p & 7) * 4;
            float4 s4 = *(const float4*)&Sb[(size_t)(q0 + row) * NS + k0 + kg];
            float4 c4 = *(const float4*)&ci[k0 + kg];
            ulonglong2 p0, p1;
            p0.x = pack2dup(__expf(s4.x) * c4.x);
            p0.y = pack2dup(__expf(s4.y) * c4.y);
            p1.x = pack2dup(__expf(s4.z) * c4.z);
            p1.y = pack2dup(__expf(s4.w) * c4.w);
            *(ulonglong2*)&As2[row * ASTR + kg]     = p0;
            *(ulonglong2*)&As2[row * ASTR + kg + 2] = p1;
        }
        // ---- stage V: 32k x 128d (1024 float4, 2/thr) ----
        #pragma unroll
        for (int u = 0; u < 2; u++) {
            int p = t + u * 512;
            int row = p >> 5, colg = p & 31;
            *(float4*)&Vs[row * ND + colg * 4] =
                *(const float4*)&Vb[(size_t)(k0 + row) * ND + colg * 4];
        }
        __syncthreads();

        // ---- inner: per kk, 2 LDS128 + 4 LDS64-bcast + 16 FFMA2 ----
        #pragma unroll
        for (int kk = 0; kk < KC; kk++) {
            ulonglong2 v0 = *(const ulonglong2*)&Vs[kk * ND + tx * 8];
            ulonglong2 v1 = *(const ulonglong2*)&Vs[kk * ND + tx * 8 + 4];
            #pragma unroll
            for (int qq = 0; qq < 4; qq++) {
                ull aa = As2[(ty * 4 + qq) * ASTR + kk];   // LDS64 broadcast
                fma2(acc2[qq][0], aa, v0.x);
                fma2(acc2[qq][1], aa, v0.y);
                fma2(acc2[qq][2], aa, v1.x);
                fma2(acc2[qq][3], aa, v1.y);
            }
        }
    }

    float* po = g_po[z];
    #pragma unroll
    for (int qq = 0; qq < 4; qq++) {
        float4 o0, o1;
        unpack2(acc2[qq][0], o0.x, o0.y);
        unpack2(acc2[qq][1], o0.z, o0.w);
        unpack2(acc2[qq][2], o1.x, o1.y);
        unpack2(acc2[qq][3], o1.z, o1.w);
        float* op = &po[(size_t)((b * NS) + q0 + ty * 4 + qq) * ND + tx * 8];
        *(float4*)op = o0;
        *(float4*)(op + 4) = o1;
    }
}

// K5: add split-k partials -> final out
__global__ void __launch_bounds__(256) k_add(float* __restrict__ Out)
{
    int p = blockIdx.x * 256 + threadIdx.x;   // float4 index
    float4 a = ((const float4*)g_po[0])[p];
    #pragma unroll
    for (int z = 1; z < KSPLIT; z++) {
        float4 c = ((const float4*)g_po[z])[p];
        a.x += c.x; a.y += c.y; a.z += c.z; a.w += c.w;
    }
    ((float4*)Out)[p] = a;
}

// ============================================================
extern "C" void kernel_launch(void* const* d_in, const int* in_sizes, int n_in,
                              void* d_out, int out_size)
{
    const float* Q   = (const float*)d_in[0];
    const float* K   = (const float*)d_in[1];
    const float* V   = (const float*)d_in[2];
    const int*   VL  = (const int*)d_in[3];
    const float* Wql = (const float*)d_in[4];
    const float* bql = (const float*)d_in[5];
    const float* Wkl = (const float*)d_in[6];
    const float* bkl = (const float*)d_in[7];
    const float* Wqh = (const float*)d_in[8];
    const float* bqh = (const float*)d_in[9];
    const float* Wkh = (const float*)d_in[10];
    const float* bkh = (const float*)d_in[11];
    float* out = (float*)d_out;

    cudaFuncSetAttribute(k_out, cudaFuncAttributeMaxDynamicSharedMemorySize,
                         SMEM_OUT_BYTES);

    k_proj<<<NB * NS, 64>>>(Q, K, Wql, bql, Wkl, bkl, Wqh, bqh, Wkh, bkh);

    dim3 g2(NS / 128, NS / 32, NB);
    k_scores<<<g2, 256>>>(VL);

    dim3 g2b(NS, NB);
    k_topk<<<g2b, 256>>>();

    dim3 g3(2, NB, NSEG);
    k_colpart<<<g3, 256>>>();
    k_colfin<<<(NB * NS) / 256, 256>>>();

    dim3 g4(NS / 128, NB, KSPLIT);
    k_out<<<g4, 512, SMEM_OUT_BYTES>>>(V);

    k_add<<<(NB * NS * ND) / 4 / 256, 256>>>(out);
}

// round 15
// speedup vs baseline: 1.1998x; 1.1998x over previous
#include <cuda_runtime.h>
#include <cstdint>

#define NB 4
#define NS 2048
#define ND 128
#define NDL 16
#define NTOP 8

#define NSEG 64
#define QSEG (NS / NSEG)   // 32

#define KSPLIT 2
#define KPART (NS / KSPLIT)   // 1024
#define KC 64
#define NCHUNK (KPART / KC)   // 16

typedef unsigned long long ull;

// ---- scratch (device globals; no allocation allowed) ----
__device__ float g_qlow[NB * NS * NDL];
__device__ float g_klow[NB * NS * NDL];
__device__ float g_sh[NB * NS];
__device__ float g_S[(size_t)NB * NS * NS];          // 64 MB corrected scores
__device__ float g_psum[NSEG * NB * NS];             // column partial sums
__device__ float g_cinv[NB * NS];
__device__ float g_po[KSPLIT][NB * NS * ND];         // split-k partial outputs

__device__ __forceinline__ float neg_inf() { return __int_as_float(0xff800000u); }

// ---- packed f32x2 helpers (FFMA2 path; ptxas won't emit this from C++) ----
__device__ __forceinline__ ull pack2(float lo, float hi) {
    ull r;
    asm("mov.b64 %0, {%1, %2};" : "=l"(r) : "f"(lo), "f"(hi));
    return r;
}
__device__ __forceinline__ ull pack2dup(float v) {
    ull r;
    asm("mov.b64 %0, {%1, %1};" : "=l"(r) : "f"(v));
    return r;
}
__device__ __forceinline__ void unpack2(ull v, float& lo, float& hi) {
    asm("mov.b64 {%0, %1}, %2;" : "=f"(lo), "=f"(hi) : "l"(v));
}
__device__ __forceinline__ void fma2(ull& acc, ull a, ull b) {
    asm("fma.rn.f32x2 %0, %1, %2, %0;" : "+l"(acc) : "l"(a), "l"(b));
}

// ---- cp.async helpers ----
__device__ __forceinline__ void cp16(void* s, const void* g) {
    uint32_t sa = (uint32_t)__cvta_generic_to_shared(s);
    asm volatile("cp.async.cg.shared.global [%0], [%1], 16;" :: "r"(sa), "l"(g) : "memory");
}
#define CP_COMMIT() asm volatile("cp.async.commit_group;" ::: "memory")
#define CP_WAIT1()  asm volatile("cp.async.wait_group 1;" ::: "memory")
#define CP_WAIT0()  asm volatile("cp.async.wait_group 0;" ::: "memory")

// ============================================================
// K1: low/high projections + per-(b,k) correction scalar sh
// ============================================================
__global__ void __launch_bounds__(64) k_proj(
    const float* __restrict__ Q, const float* __restrict__ K,
    const float* __restrict__ Wql, const float* __restrict__ bql,
    const float* __restrict__ Wkl, const float* __restrict__ bkl,
    const float* __restrict__ Wqh, const float* __restrict__ bqh,
    const float* __restrict__ Wkh, const float* __restrict__ bkh)
{
    int row = blockIdx.x;          // b*NS + i
    int t = threadIdx.x;
    __shared__ float qr[ND];
    __shared__ float kr[ND];
    __shared__ float qh[NDL];
    __shared__ float kh[NDL];

    qr[t]      = Q[(size_t)row * ND + t];
    qr[t + 64] = Q[(size_t)row * ND + t + 64];
    kr[t]      = K[(size_t)row * ND + t];
    kr[t + 64] = K[(size_t)row * ND + t + 64];
    __syncthreads();

    int g = t >> 4, j = t & 15;
    if (g == 0) {
        float a = bql[j];
        #pragma unroll 8
        for (int e = 0; e < ND; e++) a += qr[e] * Wql[e * NDL + j];
        g_qlow[(size_t)row * NDL + j] = a;
    } else if (g == 1) {
        float a = bkl[j];
        #pragma unroll 8
        for (int e = 0; e < ND; e++) a += kr[e] * Wkl[e * NDL + j];
        g_klow[(size_t)row * NDL + j] = a;
    } else if (g == 2) {
        float a = bqh[j];
        #pragma unroll 8
        for (int e = 0; e < ND; e++) a += qr[e] * Wqh[e * NDL + j];
        qh[j] = a;
    } else {
        float a = bkh[j];
        #pragma unroll 8
        for (int e = 0; e < ND; e++) a += kr[e] * Wkh[e * NDL + j];
        kh[j] = a;
    }
    __syncthreads();

    if (t == 0) {
        float s = 0.f;
        #pragma unroll
        for (int j2 = 0; j2 < NDL; j2++) s += qh[j2] * kh[j2];
        g_sh[row] = 0.25f * s;    // scale = 1/sqrt(16)
    }
}

// ============================================================
// K2a: masked low-rank scores -> g_S  (f32x2 packed: 2 q rows per lane)
// ============================================================
__global__ void __launch_bounds__(256) k_scores(const int* __restrict__ VL)
{
    __shared__ __align__(16) float ks[128][20];
    __shared__ __align__(16) float Ss[32][132];
    __shared__ int vls[128];

    int b  = blockIdx.z;
    int q0 = blockIdx.y * 32;
    int k0 = blockIdx.x * 128;
    int t  = threadIdx.x;

    {
        const float4* src = (const float4*)(g_klow + ((size_t)b * NS + k0) * NDL);
        #pragma unroll
        for (int u = 0; u < 2; u++) {
            int p = t + u * 256;
            float4 v = src[p];
            *(float4*)&ks[p >> 2][(p & 3) * 4] = v;
        }
    }
    if (t < 128) {
        int vlc = VL[b * NS + k0 + t];
        vlc = vlc < 0 ? 0 : (vlc > NS - 1 ? NS - 1 : vlc);
        vls[t] = vlc;
    }
    __syncthreads();

    int tq = t >> 4;             // 0..15
    int kg = t & 15;             // 0..15
    int ql0 = tq * 2;
    int qg0 = q0 + ql0, qg1 = qg0 + 1;

    ull qp2[NDL];
    {
        const float4* qp = (const float4*)(g_qlow + ((size_t)b * NS + qg0) * NDL);
        #pragma unroll
        for (int u = 0; u < 4; u++) {
            float4 v = qp[u];       // row 0
            float4 w = qp[u + 4];   // row 1
            qp2[u * 4 + 0] = pack2(v.x, w.x);
            qp2[u * 4 + 1] = pack2(v.y, w.y);
            qp2[u * 4 + 2] = pack2(v.z, w.z);
            qp2[u * 4 + 3] = pack2(v.w, w.w);
        }
    }

    #pragma unroll
    for (int i = 0; i < 8; i++) {
        int kl = kg + 16 * i;
        ull acc = 0ull;
        #pragma unroll
        for (int u = 0; u < 4; u++) {
            float4 kv = *(const float4*)&ks[kl][u * 4];
            fma2(acc, qp2[u * 4 + 0], pack2dup(kv.x));
            fma2(acc, qp2[u * 4 + 1], pack2dup(kv.y));
            fma2(acc, qp2[u * 4 + 2], pack2dup(kv.z));
            fma2(acc, qp2[u * 4 + 3], pack2dup(kv.w));
        }
        float a0, a1;
        unpack2(acc, a0, a1);
        a0 *= 0.25f; a1 *= 0.25f;
        int vlc = vls[kl];
        if (vlc == qg0) a0 += -1e9f;
        if (vlc == qg1) a1 += -1e9f;
        Ss[ql0][kl]     = a0;
        Ss[ql0 + 1][kl] = a1;
    }
    __syncthreads();

    #pragma unroll
    for (int u = 0; u < 4; u++) {
        int p = t + u * 256;
        int row = p >> 5, cg = p & 31;
        float4 v = *(const float4*)&Ss[row][cg * 4];
        *(float4*)(g_S + ((size_t)b * NS + q0 + row) * NS + k0 + cg * 4) = v;
    }
}

// ============================================================
// K2b: per-row top-8 and scatter sh into g_S
// ============================================================
__global__ void __launch_bounds__(256) k_topk()
{
    int q = blockIdx.x, b = blockIdx.y;
    int t = threadIdx.x;
    __shared__ __align__(16) float wk[NS];
    __shared__ float rv[8];
    __shared__ int ri[8];
    __shared__ int s_mi;
    __shared__ int topIdx[NTOP];

    float* Srow = g_S + ((size_t)b * NS + q) * NS;
    #pragma unroll
    for (int u = 0; u < 2; u++) {
        int p = t + u * 256;
        ((float4*)wk)[p] = ((const float4*)Srow)[p];
    }
    __syncthreads();

    float lv = neg_inf(); int li = 0;
    #pragma unroll
    for (int i = 0; i < 8; i++) {
        int k = t + i * 256;
        float v = wk[k];
        if (v > lv) { lv = v; li = k; }
    }

    for (int r = 0; r < NTOP; r++) {
        float mv = lv; int mi = li;
        #pragma unroll
        for (int o = 16; o > 0; o >>= 1) {
            float ov = __shfl_xor_sync(0xffffffffu, mv, o);
            int   oi = __shfl_xor_sync(0xffffffffu, mi, o);
            if (ov > mv || (ov == mv && oi < mi)) { mv = ov; mi = oi; }
        }
        if ((t & 31) == 0) { rv[t >> 5] = mv; ri[t >> 5] = mi; }
        __syncthreads();
        if (t == 0) {
            #pragma unroll
            for (int w = 1; w < 8; w++)
                if (rv[w] > mv || (rv[w] == mv && ri[w] < mi)) { mv = rv[w]; mi = ri[w]; }
            topIdx[r] = mi;
            s_mi = mi;
        }
        __syncthreads();
        if (r < NTOP - 1) {
            int gm = s_mi;
            if ((gm & 255) == t) {      // only the owner rescans
                wk[gm] = neg_inf();
                lv = neg_inf(); li = 0;
                #pragma unroll
                for (int i = 0; i < 8; i++) {
                    int k = t + i * 256;
                    float v = wk[k];
                    if (v > lv) { lv = v; li = k; }
                }
            }
        }
    }

    if (t < NTOP) {
        int idx = topIdx[t];
        Srow[idx] = g_sh[b * NS + idx];
    }
}

// ============================================================
// K3a: partial column sum of exp over q-segments
// ============================================================
__global__ void __launch_bounds__(256) k_colpart()
{
    int k  = (blockIdx.x * 256 + threadIdx.x) * 4;
    int b  = blockIdx.y;
    int seg = blockIdx.z;
    const float* Sb = g_S + (size_t)b * NS * NS;
    int q0 = seg * QSEG;

    float4 s = make_float4(0.f, 0.f, 0.f, 0.f);
    #pragma unroll 4
    for (int q = q0; q < q0 + QSEG; q++) {
        float4 v = *(const float4*)&Sb[(size_t)q * NS + k];
        s.x += __expf(v.x);
        s.y += __expf(v.y);
        s.z += __expf(v.z);
        s.w += __expf(v.w);
    }
    *(float4*)&g_psum[((size_t)seg * NB + b) * NS + k] = s;
}

// K3b: combine segments -> 1/colsum
__global__ void __launch_bounds__(256) k_colfin()
{
    int i = blockIdx.x * 256 + threadIdx.x;   // b*NS + k
    float s = 0.f;
    #pragma unroll 8
    for (int seg = 0; seg < NSEG; seg++)
        s += g_psum[(size_t)seg * (NB * NS) + i];
    g_cinv[i] = 1.0f / s;
}

// ============================================================
// K4: split-k partial out = sum_k exp(S)*cinv[k]*V[b,k,:]
// R6 inner loop (8q x 4d FFMA2, tile 64q x 128d, 256 thr) kept intact.
// New: KC=64 chunks (half the barriers), V double-buffered via cp.async,
// E register-prefetch with exp at STS, cinv staged once per block,
// A-operand loaded as (kk,kk+1) pairs -> 5 LDS per k-step instead of 9.
// smem: As2[64][66]ull (33.8KB) + Vs[2][64][128]f (64KB) + cis[1024] (4KB)
// = 101.6KB/block -> 2 blocks/SM (228KB). grid (NS/64, NB, 2) = 256 blocks.
// ============================================================
#define ASTR2 66
#define AS_BYTES   (64 * ASTR2 * 8)            // 33792
#define VS_FLOATS  (KC * ND)                   // 8192
#define VS_BYTES   (2 * VS_FLOATS * 4)         // 65536
#define CIS_BYTES  (KPART * 4)                 // 4096
#define SMEM_OUT_BYTES (AS_BYTES + VS_BYTES + CIS_BYTES)   // 103424

__global__ void __launch_bounds__(256) k_out(const float* __restrict__ V)
{
    extern __shared__ __align__(16) unsigned char smraw[];
    ull*   As2 = (ull*)smraw;                               // [64][ASTR2]
    float* Vs  = (float*)(smraw + AS_BYTES);                // [2][KC][128]
    float* cis = (float*)(smraw + AS_BYTES + VS_BYTES);     // [KPART]

    int b  = blockIdx.y;
    int q0 = blockIdx.x * 64;
    int z  = blockIdx.z;
    int t  = threadIdx.x;
    int tx = t & 31;     // d group: d = tx*4
    int ty = t >> 5;     // q group: q = q0 + ty*8 + qq

    const float* Sb = g_S + (size_t)b * NS * NS;
    const float* Vb = V + (size_t)b * NS * ND;
    int kbeg = z * KPART;

    // staging maps
    int er   = t >> 2;          // E row 0..63
    int ekg  = (t & 3) * 16;    // E col base (16 consecutive k per thread)

    // ---- preamble: cinv slice -> smem ----
    {
        const float4* cg = (const float4*)(g_cinv + b * NS + kbeg);
        ((float4*)cis)[t] = cg[t];                          // 256*16B = 4KB
    }

    // ---- preamble: V chunk0 cp.async, E chunk0 -> regs ----
    #pragma unroll
    for (int u = 0; u < 8; u++) {
        int p = t + u * 256;
        int row = p >> 5, colg = p & 31;
        cp16(&Vs[row * ND + colg * 4], &Vb[(size_t)(kbeg + row) * ND + colg * 4]);
    }
    CP_COMMIT();

    float4 eR[4];
    #pragma unroll
    for (int u = 0; u < 4; u++)
        eR[u] = *(const float4*)&Sb[(size_t)(q0 + er) * NS + kbeg + ekg + u * 4];

    __syncthreads();   // cis visible to all before first staging

    ull acc2[8][2];
    #pragma unroll
    for (int i = 0; i < 8; i++) { acc2[i][0] = 0ull; acc2[i][1] = 0ull; }

    for (int c = 0; c < NCHUNK; c++) {
        int buf = c & 1;
        // ---- stage E (exp * cinv, dup-packed) from regs ----
        {
            const float* cl = cis + c * KC + ekg;
            #pragma unroll
            for (int u = 0; u < 4; u++) {
                float4 c4 = *(const float4*)&cl[u * 4];
                ulonglong2 p0, p1;
                p0.x = pack2dup(__expf(eR[u].x) * c4.x);
                p0.y = pack2dup(__expf(eR[u].y) * c4.y);
                p1.x = pack2dup(__expf(eR[u].z) * c4.z);
                p1.y = pack2dup(__expf(eR[u].w) * c4.w);
                *(ulonglong2*)&As2[er * ASTR2 + ekg + u * 4]     = p0;
                *(ulonglong2*)&As2[er * ASTR2 + ekg + u * 4 + 2] = p1;
            }
        }
        // ---- prefetch next chunk: E -> regs, V -> cp.async other buffer ----
        if (c + 1 < NCHUNK) {
            int k1 = kbeg + (c + 1) * KC;
            #pragma unroll
            for (int u = 0; u < 8; u++) {
                int p = t + u * 256;
                int row = p >> 5, colg = p & 31;
                cp16(&Vs[(buf ^ 1) * VS_FLOATS + row * ND + colg * 4],
                     &Vb[(size_t)(k1 + row) * ND + colg * 4]);
            }
            CP_COMMIT();
            #pragma unroll
            for (int u = 0; u < 4; u++)
                eR[u] = *(const float4*)&Sb[(size_t)(q0 + er) * NS + k1 + ekg + u * 4];
            CP_WAIT1();
        } else {
            CP_WAIT0();
        }
        __syncthreads();

        // ---- compute: R6 8q x 4d loop, A loaded as (kk,kk+1) pairs ----
        const float* Vsb = Vs + buf * VS_FLOATS;
        #pragma unroll 4
        for (int kk = 0; kk < KC; kk += 2) {
            ulonglong2 v0 = *(const ulonglong2*)&Vsb[kk * ND + tx * 4];
            ulonglong2 v1 = *(const ulonglong2*)&Vsb[(kk + 1) * ND + tx * 4];
            #pragma unroll
            for (int qq = 0; qq < 8; qq++) {
                ulonglong2 ap = *(const ulonglong2*)&As2[(ty * 8 + qq) * ASTR2 + kk];
                fma2(acc2[qq][0], ap.x, v0.x);
                fma2(acc2[qq][1], ap.x, v0.y);
                fma2(acc2[qq][0], ap.y, v1.x);
                fma2(acc2[qq][1], ap.y, v1.y);
            }
        }
        __syncthreads();
    }

    float* po = g_po[z];
    #pragma unroll
    for (int qq = 0; qq < 8; qq++) {
        float4 o;
        unpack2(acc2[qq][0], o.x, o.y);
        unpack2(acc2[qq][1], o.z, o.w);
        *(float4*)&po[(size_t)((b * NS) + q0 + ty * 8 + qq) * ND + tx * 4] = o;
    }
}

// K5: add split-k partials -> final out
__global__ void __launch_bounds__(256) k_add(float* __restrict__ Out)
{
    int p = blockIdx.x * 256 + threadIdx.x;   // float4 index
    float4 a = ((const float4*)g_po[0])[p];
    #pragma unroll
    for (int z = 1; z < KSPLIT; z++) {
        float4 c = ((const float4*)g_po[z])[p];
        a.x += c.x; a.y += c.y; a.z += c.z; a.w += c.w;
    }
    ((float4*)Out)[p] = a;
}

// ============================================================
extern "C" void kernel_launch(void* const* d_in, const int* in_sizes, int n_in,
                              void* d_out, int out_size)
{
    const float* Q   = (const float*)d_in[0];
    const float* K   = (const float*)d_in[1];
    const float* V   = (const float*)d_in[2];
    const int*   VL  = (const int*)d_in[3];
    const float* Wql = (const float*)d_in[4];
    const float* bql = (const float*)d_in[5];
    const float* Wkl = (const float*)d_in[6];
    const float* bkl = (const float*)d_in[7];
    const float* Wqh = (const float*)d_in[8];
    const float* bqh = (const float*)d_in[9];
    const float* Wkh = (const float*)d_in[10];
    const float* bkh = (const float*)d_in[11];
    float* out = (float*)d_out;

    cudaFuncSetAttribute(k_out, cudaFuncAttributeMaxDynamicSharedMemorySize,
                         SMEM_OUT_BYTES);

    k_proj<<<NB * NS, 64>>>(Q, K, Wql, bql, Wkl, bkl, Wqh, bqh, Wkh, bkh);

    dim3 g2(NS / 128, NS / 32, NB);
    k_scores<<<g2, 256>>>(VL);

    dim3 g2b(NS, NB);
    k_topk<<<g2b, 256>>>();

    dim3 g3(2, NB, NSEG);
    k_colpart<<<g3, 256>>>();
    k_colfin<<<(NB * NS) / 256, 256>>>();

    dim3 g4(NS / 64, NB, KSPLIT);
    k_out<<<g4, 256, SMEM_OUT_BYTES>>>(V);

    k_add<<<(NB * NS * ND) / 4 / 256, 256>>>(out);
}

// round 16
// speedup vs baseline: 1.6062x; 1.3387x over previous
#include <cuda_runtime.h>
#include <cuda_bf16.h>
#include <cstdint>

#define NB 4
#define NS 2048
#define ND 128
#define NDL 16
#define NTOP 8

#define NSEG 64
#define QSEG (NS / NSEG)   // 32

#define KSPLIT 2
#define KPART (NS / KSPLIT)   // 1024
#define KC 64
#define NCHUNK (KPART / KC)   // 16

typedef unsigned long long ull;
typedef unsigned short u16;

// ---- scratch (device globals; no allocation allowed) ----
__device__ float g_qlow[NB * NS * NDL];
__device__ float g_klow[NB * NS * NDL];
__device__ float g_sh[NB * NS];
__device__ float g_S[(size_t)NB * NS * NS];          // 64 MB corrected scores
__device__ float g_psum[NSEG * NB * NS];             // column partial sums
__device__ float g_cinv[NB * NS];
__device__ u16   g_Eh[(size_t)NB * NS * NS];         // exp(S) bf16 hi (32 MB)
__device__ u16   g_El[(size_t)NB * NS * NS];         // exp(S) bf16 lo (32 MB)
__device__ u16   g_Vth[NB * ND * NS];                // (V*cinv)^T bf16 hi (2 MB)
__device__ u16   g_Vtl[NB * ND * NS];                // (V*cinv)^T bf16 lo (2 MB)
__device__ float g_po[KSPLIT][NB * NS * ND];         // split-k partial outputs

__device__ __forceinline__ float neg_inf() { return __int_as_float(0xff800000u); }

// ---- packed f32x2 helpers ----
__device__ __forceinline__ ull pack2(float lo, float hi) {
    ull r;
    asm("mov.b64 %0, {%1, %2};" : "=l"(r) : "f"(lo), "f"(hi));
    return r;
}
__device__ __forceinline__ ull pack2dup(float v) {
    ull r;
    asm("mov.b64 %0, {%1, %1};" : "=l"(r) : "f"(v));
    return r;
}
__device__ __forceinline__ void unpack2(ull v, float& lo, float& hi) {
    asm("mov.b64 {%0, %1}, %2;" : "=f"(lo), "=f"(hi) : "l"(v));
}
__device__ __forceinline__ void fma2(ull& acc, ull a, ull b) {
    asm("fma.rn.f32x2 %0, %1, %2, %0;" : "+l"(acc) : "l"(a), "l"(b));
}

// ---- bf16 helpers ----
__device__ __forceinline__ u16 bf16bits(float x) {
    __nv_bfloat16 h = __float2bfloat16(x);
    return *(u16*)&h;
}
__device__ __forceinline__ float bf16val(u16 u) {
    unsigned v = (unsigned)u << 16;
    return __uint_as_float(v);
}

// ---- bf16 mma (R10-verified mapping) ----
__device__ __forceinline__ void mma16816(float* c, const unsigned* a, const unsigned* b) {
    asm volatile(
        "mma.sync.aligned.m16n8k16.row.col.f32.bf16.bf16.f32 "
        "{%0,%1,%2,%3}, {%4,%5,%6,%7}, {%8,%9}, {%0,%1,%2,%3};"
        : "+f"(c[0]), "+f"(c[1]), "+f"(c[2]), "+f"(c[3])
        : "r"(a[0]), "r"(a[1]), "r"(a[2]), "r"(a[3]), "r"(b[0]), "r"(b[1]));
}

// ---- cp.async helpers ----
__device__ __forceinline__ void cp16(void* s, const void* g) {
    uint32_t sa = (uint32_t)__cvta_generic_to_shared(s);
    asm volatile("cp.async.cg.shared.global [%0], [%1], 16;" :: "r"(sa), "l"(g) : "memory");
}
#define CP_COMMIT() asm volatile("cp.async.commit_group;" ::: "memory")
#define CP_WAIT1()  asm volatile("cp.async.wait_group 1;" ::: "memory")
#define CP_WAIT0()  asm volatile("cp.async.wait_group 0;" ::: "memory")

// ============================================================
// K1: low/high projections + per-(b,k) correction scalar sh
// ============================================================
__global__ void __launch_bounds__(64) k_proj(
    const float* __restrict__ Q, const float* __restrict__ K,
    const float* __restrict__ Wql, const float* __restrict__ bql,
    const float* __restrict__ Wkl, const float* __restrict__ bkl,
    const float* __restrict__ Wqh, const float* __restrict__ bqh,
    const float* __restrict__ Wkh, const float* __restrict__ bkh)
{
    int row = blockIdx.x;          // b*NS + i
    int t = threadIdx.x;
    __shared__ float qr[ND];
    __shared__ float kr[ND];
    __shared__ float qh[NDL];
    __shared__ float kh[NDL];

    qr[t]      = Q[(size_t)row * ND + t];
    qr[t + 64] = Q[(size_t)row * ND + t + 64];
    kr[t]      = K[(size_t)row * ND + t];
    kr[t + 64] = K[(size_t)row * ND + t + 64];
    __syncthreads();

    int g = t >> 4, j = t & 15;
    if (g == 0) {
        float a = bql[j];
        #pragma unroll 8
        for (int e = 0; e < ND; e++) a += qr[e] * Wql[e * NDL + j];
        g_qlow[(size_t)row * NDL + j] = a;
    } else if (g == 1) {
        float a = bkl[j];
        #pragma unroll 8
        for (int e = 0; e < ND; e++) a += kr[e] * Wkl[e * NDL + j];
        g_klow[(size_t)row * NDL + j] = a;
    } else if (g == 2) {
        float a = bqh[j];
        #pragma unroll 8
        for (int e = 0; e < ND; e++) a += qr[e] * Wqh[e * NDL + j];
        qh[j] = a;
    } else {
        float a = bkh[j];
        #pragma unroll 8
        for (int e = 0; e < ND; e++) a += kr[e] * Wkh[e * NDL + j];
        kh[j] = a;
    }
    __syncthreads();

    if (t == 0) {
        float s = 0.f;
        #pragma unroll
        for (int j2 = 0; j2 < NDL; j2++) s += qh[j2] * kh[j2];
        g_sh[row] = 0.25f * s;    // scale = 1/sqrt(16)
    }
}

// ============================================================
// K2a: masked low-rank scores -> g_S
// ============================================================
__global__ void __launch_bounds__(256) k_scores(const int* __restrict__ VL)
{
    __shared__ __align__(16) float ks[128][20];
    __shared__ __align__(16) float Ss[32][132];
    __shared__ int vls[128];

    int b  = blockIdx.z;
    int q0 = blockIdx.y * 32;
    int k0 = blockIdx.x * 128;
    int t  = threadIdx.x;

    {
        const float4* src = (const float4*)(g_klow + ((size_t)b * NS + k0) * NDL);
        #pragma unroll
        for (int u = 0; u < 2; u++) {
            int p = t + u * 256;
            float4 v = src[p];
            *(float4*)&ks[p >> 2][(p & 3) * 4] = v;
        }
    }
    if (t < 128) {
        int vlc = VL[b * NS + k0 + t];
        vlc = vlc < 0 ? 0 : (vlc > NS - 1 ? NS - 1 : vlc);
        vls[t] = vlc;
    }
    __syncthreads();

    int tq = t >> 4;
    int kg = t & 15;
    int ql0 = tq * 2;
    int qg0 = q0 + ql0, qg1 = qg0 + 1;

    ull qp2[NDL];
    {
        const float4* qp = (const float4*)(g_qlow + ((size_t)b * NS + qg0) * NDL);
        #pragma unroll
        for (int u = 0; u < 4; u++) {
            float4 v = qp[u];
            float4 w = qp[u + 4];
            qp2[u * 4 + 0] = pack2(v.x, w.x);
            qp2[u * 4 + 1] = pack2(v.y, w.y);
            qp2[u * 4 + 2] = pack2(v.z, w.z);
            qp2[u * 4 + 3] = pack2(v.w, w.w);
        }
    }

    #pragma unroll
    for (int i = 0; i < 8; i++) {
        int kl = kg + 16 * i;
        ull acc = 0ull;
        #pragma unroll
        for (int u = 0; u < 4; u++) {
            float4 kv = *(const float4*)&ks[kl][u * 4];
            fma2(acc, qp2[u * 4 + 0], pack2dup(kv.x));
            fma2(acc, qp2[u * 4 + 1], pack2dup(kv.y));
            fma2(acc, qp2[u * 4 + 2], pack2dup(kv.z));
            fma2(acc, qp2[u * 4 + 3], pack2dup(kv.w));
        }
        float a0, a1;
        unpack2(acc, a0, a1);
        a0 *= 0.25f; a1 *= 0.25f;
        int vlc = vls[kl];
        if (vlc == qg0) a0 += -1e9f;
        if (vlc == qg1) a1 += -1e9f;
        Ss[ql0][kl]     = a0;
        Ss[ql0 + 1][kl] = a1;
    }
    __syncthreads();

    #pragma unroll
    for (int u = 0; u < 4; u++) {
        int p = t + u * 256;
        int row = p >> 5, cg = p & 31;
        float4 v = *(const float4*)&Ss[row][cg * 4];
        *(float4*)(g_S + ((size_t)b * NS + q0 + row) * NS + k0 + cg * 4) = v;
    }
}

// ============================================================
// K2b: per-row top-8 and scatter sh into g_S
// ============================================================
__global__ void __launch_bounds__(256) k_topk()
{
    int q = blockIdx.x, b = blockIdx.y;
    int t = threadIdx.x;
    __shared__ __align__(16) float wk[NS];
    __shared__ float rv[8];
    __shared__ int ri[8];
    __shared__ int s_mi;
    __shared__ int topIdx[NTOP];

    float* Srow = g_S + ((size_t)b * NS + q) * NS;
    #pragma unroll
    for (int u = 0; u < 2; u++) {
        int p = t + u * 256;
        ((float4*)wk)[p] = ((const float4*)Srow)[p];
    }
    __syncthreads();

    float lv = neg_inf(); int li = 0;
    #pragma unroll
    for (int i = 0; i < 8; i++) {
        int k = t + i * 256;
        float v = wk[k];
        if (v > lv) { lv = v; li = k; }
    }

    for (int r = 0; r < NTOP; r++) {
        float mv = lv; int mi = li;
        #pragma unroll
        for (int o = 16; o > 0; o >>= 1) {
            float ov = __shfl_xor_sync(0xffffffffu, mv, o);
            int   oi = __shfl_xor_sync(0xffffffffu, mi, o);
            if (ov > mv || (ov == mv && oi < mi)) { mv = ov; mi = oi; }
        }
        if ((t & 31) == 0) { rv[t >> 5] = mv; ri[t >> 5] = mi; }
        __syncthreads();
        if (t == 0) {
            #pragma unroll
            for (int w = 1; w < 8; w++)
                if (rv[w] > mv || (rv[w] == mv && ri[w] < mi)) { mv = rv[w]; mi = ri[w]; }
            topIdx[r] = mi;
            s_mi = mi;
        }
        __syncthreads();
        if (r < NTOP - 1) {
            int gm = s_mi;
            if ((gm & 255) == t) {
                wk[gm] = neg_inf();
                lv = neg_inf(); li = 0;
                #pragma unroll
                for (int i = 0; i < 8; i++) {
                    int k = t + i * 256;
                    float v = wk[k];
                    if (v > lv) { lv = v; li = k; }
                }
            }
        }
    }

    if (t < NTOP) {
        int idx = topIdx[t];
        Srow[idx] = g_sh[b * NS + idx];
    }
}

// ============================================================
// K3a: column partial sums of exp + write E in bf16 hi/lo
// grid (2, NB, NSEG); thread = one float4 of columns
// ============================================================
__global__ void __launch_bounds__(256) k_colpart()
{
    int k  = (blockIdx.x * 256 + threadIdx.x) * 4;
    int b  = blockIdx.y;
    int seg = blockIdx.z;
    const float* Sb = g_S + (size_t)b * NS * NS;
    int q0 = seg * QSEG;

    float4 s = make_float4(0.f, 0.f, 0.f, 0.f);
    #pragma unroll 4
    for (int q = q0; q < q0 + QSEG; q++) {
        size_t off = (size_t)q * NS + k;
        float4 v = *(const float4*)&Sb[off];
        float e0 = __expf(v.x), e1 = __expf(v.y);
        float e2 = __expf(v.z), e3 = __expf(v.w);
        s.x += e0; s.y += e1; s.z += e2; s.w += e3;

        u16 h0 = bf16bits(e0), h1 = bf16bits(e1);
        u16 h2 = bf16bits(e2), h3 = bf16bits(e3);
        uint2 hv;
        hv.x = (unsigned)h0 | ((unsigned)h1 << 16);
        hv.y = (unsigned)h2 | ((unsigned)h3 << 16);
        u16 l0 = bf16bits(e0 - bf16val(h0));
        u16 l1 = bf16bits(e1 - bf16val(h1));
        u16 l2 = bf16bits(e2 - bf16val(h2));
        u16 l3 = bf16bits(e3 - bf16val(h3));
        uint2 lv2;
        lv2.x = (unsigned)l0 | ((unsigned)l1 << 16);
        lv2.y = (unsigned)l2 | ((unsigned)l3 << 16);
        *(uint2*)&g_Eh[(size_t)b * NS * NS + off] = hv;
        *(uint2*)&g_El[(size_t)b * NS * NS + off] = lv2;
    }
    *(float4*)&g_psum[((size_t)seg * NB + b) * NS + k] = s;
}

// K3b: combine segments -> 1/colsum
__global__ void __launch_bounds__(256) k_colfin()
{
    int i = blockIdx.x * 256 + threadIdx.x;   // b*NS + k
    float s = 0.f;
    #pragma unroll 8
    for (int seg = 0; seg < NSEG; seg++)
        s += g_psum[(size_t)seg * (NB * NS) + i];
    g_cinv[i] = 1.0f / s;
}

// ============================================================
// K3c: Vt prep: Vt[b][d][k] = bf16split(V[b][k][d] * cinv[b][k])
// grid (NS/32, ND/32, NB); 256 threads; smem transpose
// ============================================================
__global__ void __launch_bounds__(256) k_vprep(const float* __restrict__ V)
{
    __shared__ float Vs[32][33];
    __shared__ float cis[32];

    int k0 = blockIdx.x * 32;
    int d0 = blockIdx.y * 32;
    int b  = blockIdx.z;
    int t  = threadIdx.x;

    {
        int row = t >> 3, cg = (t & 7) * 4;      // row = k-local, cg = d-local
        float4 v = *(const float4*)&V[(size_t)(b * NS + k0 + row) * ND + d0 + cg];
        Vs[row][cg] = v.x; Vs[row][cg + 1] = v.y;
        Vs[row][cg + 2] = v.z; Vs[row][cg + 3] = v.w;
    }
    if (t < 32) cis[t] = g_cinv[b * NS + k0 + t];
    __syncthreads();

    {
        int drow = t >> 3, kg = (t & 7) * 4;     // drow = d-local, kg = k-local
        float e0 = Vs[kg][drow]     * cis[kg];
        float e1 = Vs[kg + 1][drow] * cis[kg + 1];
        float e2 = Vs[kg + 2][drow] * cis[kg + 2];
        float e3 = Vs[kg + 3][drow] * cis[kg + 3];
        u16 h0 = bf16bits(e0), h1 = bf16bits(e1);
        u16 h2 = bf16bits(e2), h3 = bf16bits(e3);
        uint2 hv;
        hv.x = (unsigned)h0 | ((unsigned)h1 << 16);
        hv.y = (unsigned)h2 | ((unsigned)h3 << 16);
        u16 l0 = bf16bits(e0 - bf16val(h0));
        u16 l1 = bf16bits(e1 - bf16val(h1));
        u16 l2 = bf16bits(e2 - bf16val(h2));
        u16 l3 = bf16bits(e3 - bf16val(h3));
        uint2 lv2;
        lv2.x = (unsigned)l0 | ((unsigned)l1 << 16);
        lv2.y = (unsigned)l2 | ((unsigned)l3 << 16);
        size_t off = (size_t)(b * ND + d0 + drow) * NS + k0 + kg;
        *(uint2*)&g_Vth[off] = hv;
        *(uint2*)&g_Vtl[off] = lv2;
    }
}

// ============================================================
// K4: tensor-core out = E @ Vt^T with bf16 hi/lo compensation.
// grid (NS/64, NB, KSPLIT) = 256 blocks; 256 threads = 8 warps.
// Warp (wid&3)->16q, (wid>>2)->64d. Chunk KC=64 k, double-buffered cp.async.
// All operands pre-converted bf16 in gmem; staging is pure copy.
// Padded stride 72 ushorts -> conflict-free fragment LDS32.
// ============================================================
#define EST 72
#define EH_OFF 0
#define EL_OFF (64 * EST)                 // 4608 ush
#define VH_OFF (2 * 64 * EST)             // 9216
#define VL_OFF (VH_OFF + 128 * EST)       // 18432
#define BUF_USH (VL_OFF + 128 * EST)      // 27648 ush = 55296 B
#define SMEM_OUT_BYTES (2 * BUF_USH * 2)  // 110592 B

__global__ void __launch_bounds__(256) k_out()
{
    extern __shared__ __align__(16) u16 smu[];

    int b  = blockIdx.y;
    int q0 = blockIdx.x * 64;
    int z  = blockIdx.z;
    int t  = threadIdx.x;
    int lane = t & 31;
    int wid  = t >> 5;
    int mo  = (wid & 3) * 16;    // warp q offset
    int dwo = (wid >> 2) * 64;   // warp d offset
    int kbeg = z * KPART;

    const u16* Ehg = g_Eh + (size_t)b * NS * NS;
    const u16* Elg = g_El + (size_t)b * NS * NS;
    const u16* Vhg = g_Vth + (size_t)b * ND * NS;
    const u16* Vlg = g_Vtl + (size_t)b * ND * NS;

    float acc[8][4];
    #pragma unroll
    for (int i = 0; i < 8; i++)
        #pragma unroll
        for (int j = 0; j < 4; j++) acc[i][j] = 0.f;

    // staging maps (per thread): E: 2x (row,ch); V: 4x (row,ch); ch = 16B unit
    // E rows 64, 8 chunks/row -> 512 cp16; V rows 128 -> 1024 cp16
    auto stage = [&](int buf, int k0) {
        u16* sb = smu + buf * BUF_USH;
        #pragma unroll
        for (int u = 0; u < 2; u++) {
            int p = t + u * 256;
            int row = p >> 3, ch = p & 7;
            cp16(sb + EH_OFF + row * EST + ch * 8,
                 Ehg + (size_t)(q0 + row) * NS + k0 + ch * 8);
            cp16(sb + EL_OFF + row * EST + ch * 8,
                 Elg + (size_t)(q0 + row) * NS + k0 + ch * 8);
        }
        #pragma unroll
        for (int u = 0; u < 4; u++) {
            int p = t + u * 256;
            int row = p >> 3, ch = p & 7;
            cp16(sb + VH_OFF + row * EST + ch * 8,
                 Vhg + (size_t)row * NS + k0 + ch * 8);
            cp16(sb + VL_OFF + row * EST + ch * 8,
                 Vlg + (size_t)row * NS + k0 + ch * 8);
        }
        CP_COMMIT();
    };

    stage(0, kbeg);

    for (int c = 0; c < NCHUNK; c++) {
        int buf = c & 1;
        if (c + 1 < NCHUNK) {
            stage(buf ^ 1, kbeg + (c + 1) * KC);
            CP_WAIT1();
        } else {
            CP_WAIT0();
        }
        __syncthreads();

        const u16* EhS = smu + buf * BUF_USH + EH_OFF;
        const u16* ElS = smu + buf * BUF_USH + EL_OFF;
        const u16* VhS = smu + buf * BUF_USH + VH_OFF;
        const u16* VlS = smu + buf * BUF_USH + VL_OFF;

        #pragma unroll
        for (int ks = 0; ks < KC; ks += 16) {
            int c0 = (lane & 3) * 2 + ks;
            int r  = mo + (lane >> 2);
            unsigned ah[4], al[4];
            ah[0] = *(const unsigned*)&EhS[r * EST + c0];
            ah[1] = *(const unsigned*)&EhS[(r + 8) * EST + c0];
            ah[2] = *(const unsigned*)&EhS[r * EST + c0 + 8];
            ah[3] = *(const unsigned*)&EhS[(r + 8) * EST + c0 + 8];
            al[0] = *(const unsigned*)&ElS[r * EST + c0];
            al[1] = *(const unsigned*)&ElS[(r + 8) * EST + c0];
            al[2] = *(const unsigned*)&ElS[r * EST + c0 + 8];
            al[3] = *(const unsigned*)&ElS[(r + 8) * EST + c0 + 8];
            #pragma unroll
            for (int nt = 0; nt < 8; nt++) {
                int n = dwo + nt * 8 + (lane >> 2);
                unsigned bh[2], bl[2];
                bh[0] = *(const unsigned*)&VhS[n * EST + c0];
                bh[1] = *(const unsigned*)&VhS[n * EST + c0 + 8];
                bl[0] = *(const unsigned*)&VlS[n * EST + c0];
                bl[1] = *(const unsigned*)&VlS[n * EST + c0 + 8];
                mma16816(acc[nt], ah, bh);
                mma16816(acc[nt], ah, bl);
                mma16816(acc[nt], al, bh);
            }
        }
        __syncthreads();
    }

    float* po = g_po[z];
    int r = q0 + mo + (lane >> 2);
    #pragma unroll
    for (int nt = 0; nt < 8; nt++) {
        int dcol = dwo + nt * 8 + (lane & 3) * 2;
        float2 v0 = make_float2(acc[nt][0], acc[nt][1]);
        float2 v1 = make_float2(acc[nt][2], acc[nt][3]);
        *(float2*)&po[(size_t)(b * NS + r) * ND + dcol] = v0;
        *(float2*)&po[(size_t)(b * NS + r + 8) * ND + dcol] = v1;
    }
}

// K5: add split-k partials -> final out
__global__ void __launch_bounds__(256) k_add(float* __restrict__ Out)
{
    int p = blockIdx.x * 256 + threadIdx.x;   // float4 index
    float4 a = ((const float4*)g_po[0])[p];
    #pragma unroll
    for (int z = 1; z < KSPLIT; z++) {
        float4 c = ((const float4*)g_po[z])[p];
        a.x += c.x; a.y += c.y; a.z += c.z; a.w += c.w;
    }
    ((float4*)Out)[p] = a;
}

// ============================================================
extern "C" void kernel_launch(void* const* d_in, const int* in_sizes, int n_in,
                              void* d_out, int out_size)
{
    const float* Q   = (const float*)d_in[0];
    const float* K   = (const float*)d_in[1];
    const float* V   = (const float*)d_in[2];
    const int*   VL  = (const int*)d_in[3];
    const float* Wql = (const float*)d_in[4];
    const float* bql = (const float*)d_in[5];
    const float* Wkl = (const float*)d_in[6];
    const float* bkl = (const float*)d_in[7];
    const float* Wqh = (const float*)d_in[8];
    const float* bqh = (const float*)d_in[9];
    const float* Wkh = (const float*)d_in[10];
    const float* bkh = (const float*)d_in[11];
    float* out = (float*)d_out;

    cudaFuncSetAttribute(k_out, cudaFuncAttributeMaxDynamicSharedMemorySize,
                         SMEM_OUT_BYTES);

    k_proj<<<NB * NS, 64>>>(Q, K, Wql, bql, Wkl, bkl, Wqh, bqh, Wkh, bkh);

    dim3 g2(NS / 128, NS / 32, NB);
    k_scores<<<g2, 256>>>(VL);

    dim3 g2b(NS, NB);
    k_topk<<<g2b, 256>>>();

    dim3 g3(2, NB, NSEG);
    k_colpart<<<g3, 256>>>();
    k_colfin<<<(NB * NS) / 256, 256>>>();

    dim3 gv(NS / 32, ND / 32, NB);
    k_vprep<<<gv, 256>>>(V);

    dim3 g4(NS / 64, NB, KSPLIT);
    k_out<<<g4, 256, SMEM_OUT_BYTES>>>();

    k_add<<<(NB * NS * ND) / 4 / 256, 256>>>(out);
}